// round 2
// baseline (speedup 1.0000x reference)
#include <cuda_runtime.h>
#include <cuda_bf16.h>

// Problem constants
#define PB    32    // batch
#define NN    8     // objects
#define P0    64
#define P1    128
#define P2    64
#define CC    128   // channels
#define KK    56    // permutations of (8,2)
#define F_TOT 448   // P0 + 2*P1 + 2*P2
#define BC    8     // batch chunk per block

// Scratch (no allocations allowed)
__device__ float g_t[F_TOT * CC];        // tanh(kernel), 229 KB
__device__ float g_conj[PB * KK * CC];   // per-(b,k,c) min, 917 KB

__global__ void tanh_k(const float* __restrict__ kern) {
    int idx = blockIdx.x * blockDim.x + threadIdx.x;
    if (idx < F_TOT * CC) g_t[idx] = tanhf(kern[idx]);
}

__global__ __launch_bounds__(CC) void main_k(const float* __restrict__ nullary,
                                             const float* __restrict__ unary,
                                             const float* __restrict__ binary) {
    const int k   = blockIdx.x;       // permutation index 0..55
    const int bb0 = blockIdx.y * BC;  // batch base
    const int c   = threadIdx.x;      // channel 0..127

    // Decode permutation (i, j) from itertools order: k = i*7 + j'
    const int i  = k / 7;
    const int r  = k % 7;              // j' = j - (j > i)
    const int j  = r + (r >= i);
    const int jp = r;                  // binary slot 0 column: (i, jp)
    const int ip = i - (i > j);        // binary slot 1 column: (j, ip)

    __shared__ float xs[BC][F_TOT];

    // Cooperative gather of the 448-feature input vector for BC batches
    for (int f = threadIdx.x; f < F_TOT; f += CC) {
        #pragma unroll
        for (int bb = 0; bb < BC; bb++) {
            const int b = bb0 + bb;
            float v;
            if (f < 64) {
                v = nullary[b * P0 + f];
            } else if (f < 192) {
                v = unary[(b * NN + i) * P1 + (f - 64)];
            } else if (f < 320) {
                v = unary[(b * NN + j) * P1 + (f - 192)];
            } else if (f < 384) {
                v = binary[((b * NN + i) * (NN - 1) + jp) * P2 + (f - 320)];
            } else {
                v = binary[((b * NN + j) * (NN - 1) + ip) * P2 + (f - 384)];
            }
            xs[bb][f] = v;
        }
    }
    __syncthreads();

    float m[BC];
    #pragma unroll
    for (int bb = 0; bb < BC; bb++) m[bb] = 1e30f;

    // min over all 448 features: w = x*t + (1 - t*t)
    #pragma unroll 4
    for (int f = 0; f < F_TOT; f++) {
        const float t = g_t[f * CC + c];
        const float q = fmaf(-t, t, 1.0f);
        #pragma unroll
        for (int bb = 0; bb < BC; bb++) {
            const float w = fmaf(xs[bb][f], t, q);
            m[bb] = fminf(m[bb], w);
        }
    }

    #pragma unroll
    for (int bb = 0; bb < BC; bb++) {
        g_conj[((bb0 + bb) * KK + k) * CC + c] = m[bb];
    }
}

__global__ void max_k(float* __restrict__ out) {
    const int idx = blockIdx.x * blockDim.x + threadIdx.x;  // b*CC + c
    if (idx >= PB * CC) return;
    const int b = idx / CC;
    const int c = idx % CC;
    float m = -1e30f;
    #pragma unroll
    for (int k = 0; k < KK; k++) {
        m = fmaxf(m, g_conj[(b * KK + k) * CC + c]);
    }
    out[idx] = m;
}

extern "C" void kernel_launch(void* const* d_in, const int* in_sizes, int n_in,
                              void* d_out, int out_size) {
    const float* nullary = (const float*)d_in[0];  // (32, 64)
    const float* unary   = (const float*)d_in[1];  // (32, 8, 128)
    const float* binary  = (const float*)d_in[2];  // (32, 8, 7, 64)
    const float* kern    = (const float*)d_in[3];  // (448, 128)
    float* out = (float*)d_out;                    // (32, 128)

    tanh_k<<<(F_TOT * CC + 255) / 256, 256>>>(kern);
    main_k<<<dim3(KK, PB / BC), CC>>>(nullary, unary, binary);
    max_k<<<(PB * CC + 127) / 128, 128>>>(out);
}

// round 3
// speedup vs baseline: 1.0592x; 1.0592x over previous
#include <cuda_runtime.h>
#include <cuda_bf16.h>

// Problem constants
#define PB    32    // batch
#define NN    8     // objects
#define P0    64
#define P1    128
#define P2    64
#define CC    128   // channels
#define KK    56    // permutations of (8,2)
#define F_TOT 448   // P0 + 2*P1 + 2*P2

// Scratch (allocation-free: __device__ globals)
__device__ float g_t[F_TOT * CC];      // tanh(kernel)
__device__ float g_N0[PB * CC];        // min over nullary slot
__device__ float g_U0[PB * NN * CC];   // min over unary slot0, per (b, i, c)
__device__ float g_U1[PB * NN * CC];   // min over unary slot1, per (b, j, c)
__device__ float g_B0[PB * KK * CC];   // min over binary slot0, per (b, pair m, c)
__device__ float g_B1[PB * KK * CC];   // min over binary slot1, per (b, pair m, c)

__global__ void tanh_k(const float4* __restrict__ kern) {
    int idx = blockIdx.x * blockDim.x + threadIdx.x;
    if (idx < (F_TOT * CC) / 4) {
        float4 v = kern[idx];
        float4 r;
        r.x = tanhf(v.x);
        r.y = tanhf(v.y);
        r.z = tanhf(v.z);
        r.w = tanhf(v.w);
        reinterpret_cast<float4*>(g_t)[idx] = r;
    }
}

// Grid of 146 blocks, 128 threads (thread = channel c):
//   blocks [0,56):    B0'  (pair m = blk,      t rows 320..383, 32 b-accums)
//   blocks [56,112):  B1'  (pair m = blk-56,   t rows 384..447, 32 b-accums)
//   blocks [112,128): U0   (i = r/2, b-half,   t rows  64..191, 16 b-accums)
//   blocks [128,144): U1   (j = r/2, b-half,   t rows 192..319, 16 b-accums)
//   blocks [144,146): N0   (b-half,            t rows   0..63,  16 b-accums)
__global__ __launch_bounds__(CC) void partial_k(const float* __restrict__ nullary,
                                                const float* __restrict__ unary,
                                                const float* __restrict__ binary) {
    const int blk = blockIdx.x;
    const int c   = threadIdx.x;
    __shared__ float xs[2048];  // 8 KB staging of the x vectors

    if (blk < 112) {
        // ---- binary slots: 32 batches x 64 features ----
        const bool slot1 = (blk >= 56);
        const int  m     = slot1 ? blk - 56 : blk;
        const int  i     = m / 7;
        const int  jp    = m % 7;
        const int  tbase = slot1 ? 384 : 320;

        for (int idx = c; idx < PB * P2; idx += CC) {
            const int b = idx >> 6, f = idx & 63;
            xs[idx] = binary[((b * NN + i) * (NN - 1) + jp) * P2 + f];
        }
        __syncthreads();

        float acc[PB];
        #pragma unroll
        for (int b = 0; b < PB; b++) acc[b] = 1e30f;

        #pragma unroll 2
        for (int f = 0; f < P2; f++) {
            const float t = g_t[(tbase + f) * CC + c];
            const float q = fmaf(-t, t, 1.0f);
            #pragma unroll
            for (int b = 0; b < PB; b++)
                acc[b] = fminf(acc[b], fmaf(xs[(b << 6) + f], t, q));
        }

        float* dst = slot1 ? g_B1 : g_B0;
        #pragma unroll
        for (int b = 0; b < PB; b++)
            dst[(b * KK + m) * CC + c] = acc[b];

    } else if (blk < 144) {
        // ---- unary slots: 16 batches x 128 features ----
        int r = blk - 112;
        const bool slot1 = (r >= 16);
        if (slot1) r -= 16;
        const int i     = r >> 1;
        const int b0    = (r & 1) * 16;
        const int tbase = slot1 ? 192 : 64;

        for (int idx = c; idx < 16 * P1; idx += CC) {
            const int b = idx >> 7, f = idx & 127;
            xs[idx] = unary[((b0 + b) * NN + i) * P1 + f];
        }
        __syncthreads();

        float acc[16];
        #pragma unroll
        for (int b = 0; b < 16; b++) acc[b] = 1e30f;

        #pragma unroll 2
        for (int f = 0; f < P1; f++) {
            const float t = g_t[(tbase + f) * CC + c];
            const float q = fmaf(-t, t, 1.0f);
            #pragma unroll
            for (int b = 0; b < 16; b++)
                acc[b] = fminf(acc[b], fmaf(xs[(b << 7) + f], t, q));
        }

        float* dst = slot1 ? g_U1 : g_U0;
        #pragma unroll
        for (int b = 0; b < 16; b++)
            dst[((b0 + b) * NN + i) * CC + c] = acc[b];

    } else {
        // ---- nullary slot: 16 batches x 64 features ----
        const int b0 = (blk - 144) * 16;

        for (int idx = c; idx < 16 * P0; idx += CC) {
            const int b = idx >> 6, f = idx & 63;
            xs[idx] = nullary[(b0 + b) * P0 + f];
        }
        __syncthreads();

        float acc[16];
        #pragma unroll
        for (int b = 0; b < 16; b++) acc[b] = 1e30f;

        #pragma unroll 2
        for (int f = 0; f < P0; f++) {
            const float t = g_t[f * CC + c];
            const float q = fmaf(-t, t, 1.0f);
            #pragma unroll
            for (int b = 0; b < 16; b++)
                acc[b] = fminf(acc[b], fmaf(xs[(b << 6) + f], t, q));
        }

        #pragma unroll
        for (int b = 0; b < 16; b++)
            g_N0[(b0 + b) * CC + c] = acc[b];
    }
}

// One block per batch, thread = channel. out[b,c] = max_k min(N0,U0,U1,B0,B1rev)
__global__ __launch_bounds__(CC) void combine_k(float* __restrict__ out) {
    const int b = blockIdx.x;
    const int c = threadIdx.x;

    float u0[NN], u1[NN];
    #pragma unroll
    for (int i = 0; i < NN; i++) {
        u0[i] = g_U0[(b * NN + i) * CC + c];
        u1[i] = g_U1[(b * NN + i) * CC + c];
    }
    const float n0 = g_N0[b * CC + c];

    float mx = -1e30f;
    #pragma unroll
    for (int k = 0; k < KK; k++) {
        const int i  = k / 7;
        const int r  = k % 7;
        const int j  = r + (r >= i);
        const int rv = j * 7 + (i - (i > j));  // reversed-pair index
        const float b0v = g_B0[(b * KK + k)  * CC + c];
        const float b1v = g_B1[(b * KK + rv) * CC + c];
        float v = fminf(fminf(b0v, b1v), fminf(u0[i], u1[j]));
        v = fminf(v, n0);
        mx = fmaxf(mx, v);
    }
    out[b * CC + c] = mx;
}

extern "C" void kernel_launch(void* const* d_in, const int* in_sizes, int n_in,
                              void* d_out, int out_size) {
    const float* nullary = (const float*)d_in[0];  // (32, 64)
    const float* unary   = (const float*)d_in[1];  // (32, 8, 128)
    const float* binary  = (const float*)d_in[2];  // (32, 8, 7, 64)
    const float* kern    = (const float*)d_in[3];  // (448, 128)
    float* out = (float*)d_out;                    // (32, 128)

    tanh_k<<<(F_TOT * CC / 4 + 255) / 256, 256>>>((const float4*)kern);
    partial_k<<<146, CC>>>(nullary, unary, binary);
    combine_k<<<PB, CC>>>(out);
}

// round 4
// speedup vs baseline: 2.0748x; 1.9588x over previous
#include <cuda_runtime.h>
#include <cuda_bf16.h>

// Problem constants
#define PB    32    // batch
#define NN    8     // objects
#define P0    64
#define P1    128
#define P2    64
#define CC    128   // channels
#define KK    56    // permutations of (8,2)
#define GRID  146   // 112 binary + 32 unary + 2 nullary blocks (single wave on 148 SMs)

// Scratch (allocation-free: __device__ globals)
__device__ float g_N0[PB * CC];
__device__ float g_U0[PB * NN * CC];
__device__ float g_U1[PB * NN * CC];
__device__ float g_B0[PB * KK * CC];
__device__ float g_B1[PB * KK * CC];
__device__ int   g_arrive;   // zero-init; reset at end of each launch
__device__ int   g_done;

// tanh(x) = 1 - 2/(exp(2x)+1). Safe at large |x| (exp->inf => div->0 => t=1).
__device__ __forceinline__ float fast_tanh(float x) {
    const float e = __expf(2.0f * x);
    return 1.0f - __fdividef(2.0f, e + 1.0f);
}

__global__ __launch_bounds__(CC) void fused_k(const float* __restrict__ nullary,
                                              const float* __restrict__ unary,
                                              const float* __restrict__ binary,
                                              const float* __restrict__ kern,
                                              float* __restrict__ out) {
    const int blk = blockIdx.x;
    const int c   = threadIdx.x;
    __shared__ float xs[2048];  // 8 KB x staging

    // ---------------- Phase 1: slot-partial mins ----------------
    if (blk < 112) {
        // binary slots: one pair m, 32 batches x 64 features
        const bool slot1 = (blk >= 56);
        const int  m     = slot1 ? blk - 56 : blk;
        const int  i     = m / 7;
        const int  jp    = m % 7;
        const int  tbase = slot1 ? 384 : 320;

        for (int idx = c; idx < PB * P2; idx += CC) {
            const int b = idx >> 6, f = idx & 63;
            xs[idx] = binary[((b * NN + i) * (NN - 1) + jp) * P2 + f];
        }
        __syncthreads();

        float acc[PB];
        #pragma unroll
        for (int b = 0; b < PB; b++) acc[b] = 1e30f;

        const float* krow = kern + tbase * CC + c;
        #pragma unroll 4
        for (int f = 0; f < P2; f++) {
            const float t = fast_tanh(krow[f * CC]);
            const float q = fmaf(-t, t, 1.0f);
            #pragma unroll
            for (int b = 0; b < PB; b++)
                acc[b] = fminf(acc[b], fmaf(xs[(b << 6) + f], t, q));
        }

        float* dst = slot1 ? g_B1 : g_B0;
        #pragma unroll
        for (int b = 0; b < PB; b++)
            dst[(b * KK + m) * CC + c] = acc[b];

    } else if (blk < 144) {
        // unary slots: one object i, half the batch, 128 features
        int r = blk - 112;
        const bool slot1 = (r >= 16);
        if (slot1) r -= 16;
        const int i     = r >> 1;
        const int b0    = (r & 1) * 16;
        const int tbase = slot1 ? 192 : 64;

        for (int idx = c; idx < 16 * P1; idx += CC) {
            const int b = idx >> 7, f = idx & 127;
            xs[idx] = unary[((b0 + b) * NN + i) * P1 + f];
        }
        __syncthreads();

        float acc[16];
        #pragma unroll
        for (int b = 0; b < 16; b++) acc[b] = 1e30f;

        const float* krow = kern + tbase * CC + c;
        #pragma unroll 4
        for (int f = 0; f < P1; f++) {
            const float t = fast_tanh(krow[f * CC]);
            const float q = fmaf(-t, t, 1.0f);
            #pragma unroll
            for (int b = 0; b < 16; b++)
                acc[b] = fminf(acc[b], fmaf(xs[(b << 7) + f], t, q));
        }

        float* dst = slot1 ? g_U1 : g_U0;
        #pragma unroll
        for (int b = 0; b < 16; b++)
            dst[((b0 + b) * NN + i) * CC + c] = acc[b];

    } else {
        // nullary slot: half the batch, 64 features
        const int b0 = (blk - 144) * 16;

        for (int idx = c; idx < 16 * P0; idx += CC) {
            const int b = idx >> 6, f = idx & 63;
            xs[idx] = nullary[(b0 + b) * P0 + f];
        }
        __syncthreads();

        float acc[16];
        #pragma unroll
        for (int b = 0; b < 16; b++) acc[b] = 1e30f;

        const float* krow = kern + c;
        #pragma unroll 4
        for (int f = 0; f < P0; f++) {
            const float t = fast_tanh(krow[f * CC]);
            const float q = fmaf(-t, t, 1.0f);
            #pragma unroll
            for (int b = 0; b < 16; b++)
                acc[b] = fminf(acc[b], fmaf(xs[(b << 6) + f], t, q));
        }

        #pragma unroll
        for (int b = 0; b < 16; b++)
            g_N0[(b0 + b) * CC + c] = acc[b];
    }

    // ---------------- Grid soft-barrier (single wave: GRID=146 <= 148 SMs) ----------------
    __threadfence();   // make partials visible device-wide
    __syncthreads();
    if (threadIdx.x == 0) atomicAdd(&g_arrive, 1);

    if (blk >= PB) return;   // only blocks 0..31 combine

    if (threadIdx.x == 0) {
        while (*((volatile int*)&g_arrive) != GRID) { }
    }
    __syncthreads();
    __threadfence();

    // ---------------- Phase 2: combine for batch b = blk ----------------
    {
        const int b = blk;
        float u0[NN], u1[NN];
        #pragma unroll
        for (int i = 0; i < NN; i++) {
            u0[i] = g_U0[(b * NN + i) * CC + c];
            u1[i] = g_U1[(b * NN + i) * CC + c];
        }
        const float n0 = g_N0[b * CC + c];

        float mx = -1e30f;
        #pragma unroll
        for (int k = 0; k < KK; k++) {
            const int i  = k / 7;
            const int r  = k % 7;
            const int j  = r + (r >= i);
            const int rv = j * 7 + (i - (i > j));  // reversed-pair index
            const float b0v = g_B0[(b * KK + k)  * CC + c];
            const float b1v = g_B1[(b * KK + rv) * CC + c];
            float v = fminf(fminf(b0v, b1v), fminf(u0[i], u1[j]));
            v = fminf(v, n0);
            mx = fmaxf(mx, v);
        }
        out[b * CC + c] = mx;
    }

    // ---------------- Counter reset for graph replay ----------------
    __syncthreads();
    if (threadIdx.x == 0) {
        const int old = atomicAdd(&g_done, 1);
        if (old == PB - 1) {          // last combine block resets both counters
            atomicExch(&g_arrive, 0);
            atomicExch(&g_done, 0);
        }
    }
}

extern "C" void kernel_launch(void* const* d_in, const int* in_sizes, int n_in,
                              void* d_out, int out_size) {
    const float* nullary = (const float*)d_in[0];  // (32, 64)
    const float* unary   = (const float*)d_in[1];  // (32, 8, 128)
    const float* binary  = (const float*)d_in[2];  // (32, 8, 7, 64)
    const float* kern    = (const float*)d_in[3];  // (448, 128)
    float* out = (float*)d_out;                    // (32, 128)

    fused_k<<<GRID, CC>>>(nullary, unary, binary, kern, out);
}